// round 1
// baseline (speedup 1.0000x reference)
#include <cuda_runtime.h>
#include <cuda_bf16.h>
#include <math_constants.h>

// Problem constants (fixed by setup_inputs)
#define Bq 4
#define Hq 8
#define BH 32          // B*H
#define Lq 2048
#define Dq 64
#define SK 40          // sample_k
#define NT 40          // n_top
#define SCALE 0.125f   // 1/sqrt(64)

// ---------------- scratch (device globals; no allocation) ----------------
__device__ float g_M[BH * Lq];                 // 256 KB
__device__ int   g_top[BH * NT];               // 5 KB
__device__ float g_vmean[BH * Dq];             // 8 KB
__device__ float g_scores[(size_t)BH * NT * Lq];   // 10.5 MB
__device__ float g_part[8 * BH * NT * Dq];     // 2.6 MB (k-split partials)

// ---------------- kernel 1: M[bh,l] = max_s q.k - sum_s/L ----------------
__global__ void k_M(const float* __restrict__ Q, const float* __restrict__ K,
                    const int* __restrict__ idxs) {
    int w = blockIdx.x * (blockDim.x >> 5) + (threadIdx.x >> 5);   // query id
    int lane = threadIdx.x & 31;
    if (w >= BH * Lq) return;
    int bh = w >> 11;
    int l  = w & (Lq - 1);
    const float* q = Q + (size_t)w * Dq;
    float q0 = q[lane];
    float q1 = q[lane + 32];
    const float* Kb = K + (size_t)bh * Lq * Dq;
    float mx = -CUDART_INF_F;
    float sm = 0.f;
    #pragma unroll 4
    for (int s = 0; s < SK; s++) {
        int idx = __ldg(&idxs[l * SK + s]);
        const float* kr = Kb + (size_t)idx * Dq;
        float p = q0 * __ldg(&kr[lane]) + q1 * __ldg(&kr[lane + 32]);
        #pragma unroll
        for (int o = 16; o; o >>= 1) p += __shfl_xor_sync(0xffffffffu, p, o);
        mx = fmaxf(mx, p);
        sm += p;
    }
    if (lane == 0) g_M[w] = mx - sm * (1.0f / (float)Lq);
}

// ---------------- kernel 2: top-40 per (b,h) (iterative argmax) ----------
__global__ void k_topk() {
    __shared__ float vals[Lq];
    __shared__ float wv[8];
    __shared__ int   wi[8];
    int bh = blockIdx.x;
    int t = threadIdx.x;
    for (int i = t; i < Lq; i += 256) vals[i] = g_M[bh * Lq + i];
    __syncthreads();
    int lane = t & 31, wid = t >> 5;
    for (int it = 0; it < NT; it++) {
        float bv = -CUDART_INF_F; int bi = Lq;
        for (int i = t; i < Lq; i += 256) {
            float v = vals[i];
            if (v > bv) { bv = v; bi = i; }
        }
        #pragma unroll
        for (int o = 16; o; o >>= 1) {
            float ov = __shfl_xor_sync(0xffffffffu, bv, o);
            int   oi = __shfl_xor_sync(0xffffffffu, bi, o);
            if (ov > bv || (ov == bv && oi < bi)) { bv = ov; bi = oi; }
        }
        if (lane == 0) { wv[wid] = bv; wi[wid] = bi; }
        __syncthreads();
        if (t == 0) {
            for (int wN = 1; wN < 8; wN++)
                if (wv[wN] > bv || (wv[wN] == bv && wi[wN] < bi)) { bv = wv[wN]; bi = wi[wN]; }
            g_top[bh * NT + it] = bi;
            vals[bi] = -CUDART_INF_F;
        }
        __syncthreads();
    }
}

// ---------------- kernel 3: V mean over L per (b,h) ----------------------
__global__ void k_vmean(const float* __restrict__ V) {
    int bh = blockIdx.x;
    int t = threadIdx.x;
    int d = t & 63, part = t >> 6;              // 4 parts of 512 rows
    const float* Vb = V + (size_t)bh * Lq * Dq;
    float s = 0.f;
    int k0 = part * 512;
    for (int k = k0; k < k0 + 512; k++) s += Vb[(size_t)k * Dq + d];
    __shared__ float ps[256];
    ps[t] = s;
    __syncthreads();
    if (t < 64)
        g_vmean[bh * Dq + t] = (ps[t] + ps[t + 64] + ps[t + 128] + ps[t + 192]) * (1.0f / (float)Lq);
}

// ---------------- kernel 4: broadcast V_mean to every output row ---------
__global__ void k_fill(float* __restrict__ out) {
    int i = blockIdx.x * blockDim.x + threadIdx.x;    // BH*L*D = 4194304 total
    out[i] = g_vmean[((i >> 17) << 6) | (i & 63)];
}

// ---------------- kernel 5: scores_top = (Q_top @ K^T) * scale -----------
// grid: BH * 16 key-tiles; block 256. tile = 40u x 128k, K-dim = 64 in one slab.
__global__ void k_scores(const float* __restrict__ Q, const float* __restrict__ K) {
    __shared__ float qs[NT * Dq];           // 40x64
    __shared__ float Kt[Dq * 132];          // transposed [d][k], padded row 132
    int bh = blockIdx.x >> 4;
    int kt = blockIdx.x & 15;
    int t = threadIdx.x;
    const float* Qb = Q + (size_t)bh * Lq * Dq;
    const float* Kb = K + (size_t)bh * Lq * Dq;
    // load 40 top queries
    for (int j = t; j < NT * Dq; j += 256) {
        int u = j >> 6, d = j & 63;
        int qi = __ldg(&g_top[bh * NT + u]);
        qs[j] = Qb[(size_t)qi * Dq + d];
    }
    // load 128 key rows, transposed
    for (int j = t; j < 128 * Dq; j += 256) {
        int r = j >> 6, d = j & 63;
        Kt[d * 132 + r] = Kb[(size_t)(kt * 128 + r) * Dq + d];
    }
    __syncthreads();
    int tu = t >> 5;          // 0..7 -> 5 queries each (same per warp: broadcast qs reads)
    int tk = t & 31;          // 4 keys each
    float acc[5][4] = {};
    #pragma unroll 8
    for (int d = 0; d < Dq; d++) {
        float a[5];
        #pragma unroll
        for (int i = 0; i < 5; i++) a[i] = qs[(tu * 5 + i) * Dq + d];
        float4 b = *(const float4*)&Kt[d * 132 + tk * 4];
        #pragma unroll
        for (int i = 0; i < 5; i++) {
            acc[i][0] = fmaf(a[i], b.x, acc[i][0]);
            acc[i][1] = fmaf(a[i], b.y, acc[i][1]);
            acc[i][2] = fmaf(a[i], b.z, acc[i][2]);
            acc[i][3] = fmaf(a[i], b.w, acc[i][3]);
        }
    }
    #pragma unroll
    for (int i = 0; i < 5; i++) {
        int u = tu * 5 + i;
        float4 r;
        r.x = acc[i][0] * SCALE; r.y = acc[i][1] * SCALE;
        r.z = acc[i][2] * SCALE; r.w = acc[i][3] * SCALE;
        *(float4*)&g_scores[((size_t)(bh * NT + u)) * Lq + kt * 128 + tk * 4] = r;
    }
}

// ---------------- kernel 6: softmax over 2048 keys per top row -----------
__global__ void k_softmax() {
    __shared__ float red[8];
    int row = blockIdx.x;                  // BH*NT = 1280 rows
    float* s = g_scores + (size_t)row * Lq;
    int t = threadIdx.x, lane = t & 31, wid = t >> 5;
    float mx = -CUDART_INF_F;
    for (int i = t; i < Lq; i += 256) mx = fmaxf(mx, s[i]);
    #pragma unroll
    for (int o = 16; o; o >>= 1) mx = fmaxf(mx, __shfl_xor_sync(0xffffffffu, mx, o));
    if (lane == 0) red[wid] = mx;
    __syncthreads();
    mx = red[0];
    #pragma unroll
    for (int i = 1; i < 8; i++) mx = fmaxf(mx, red[i]);
    __syncthreads();
    float sum = 0.f;
    for (int i = t; i < Lq; i += 256) {
        float e = __expf(s[i] - mx);
        s[i] = e;
        sum += e;
    }
    #pragma unroll
    for (int o = 16; o; o >>= 1) sum += __shfl_xor_sync(0xffffffffu, sum, o);
    if (lane == 0) red[wid] = sum;
    __syncthreads();
    sum = 0.f;
    #pragma unroll
    for (int i = 0; i < 8; i++) sum += red[i];
    float inv = 1.0f / sum;
    for (int i = t; i < Lq; i += 256) s[i] *= inv;
}

// ---------------- kernel 7: ctx partial = attn @ V (k-split) -------------
// grid: BH * 8 k-splits (256 keys each); block 256.
__global__ void k_ctx(const float* __restrict__ V) {
    __shared__ float Vs[128 * Dq];          // 32 KB
    int bh = blockIdx.x >> 3;
    int ks = blockIdx.x & 7;
    int t = threadIdx.x;
    int tu = t >> 5;                        // 0..7 -> 5 queries each
    int td = t & 31;                        // 2 d's each (float2)
    const float* Vb = V + (size_t)bh * Lq * Dq;
    const float* Sb = g_scores + (size_t)bh * NT * Lq;
    float acc[5][2] = {};
    for (int sub = 0; sub < 2; sub++) {
        int k0 = ks * 256 + sub * 128;
        __syncthreads();
        for (int j = t; j < 128 * Dq; j += 256) Vs[j] = Vb[(size_t)k0 * Dq + j];
        __syncthreads();
        #pragma unroll 4
        for (int kk = 0; kk < 128; kk++) {
            float a[5];
            #pragma unroll
            for (int i = 0; i < 5; i++)
                a[i] = __ldg(&Sb[(size_t)(tu * 5 + i) * Lq + k0 + kk]);
            float2 v = *(const float2*)&Vs[kk * Dq + td * 2];
            #pragma unroll
            for (int i = 0; i < 5; i++) {
                acc[i][0] = fmaf(a[i], v.x, acc[i][0]);
                acc[i][1] = fmaf(a[i], v.y, acc[i][1]);
            }
        }
    }
    #pragma unroll
    for (int i = 0; i < 5; i++) {
        int u = tu * 5 + i;
        float2 r; r.x = acc[i][0]; r.y = acc[i][1];
        *(float2*)&g_part[(((size_t)ks * BH + bh) * NT + u) * Dq + td * 2] = r;
    }
}

// ---------------- kernel 8: sum partials, scatter into output rows -------
__global__ void k_scatter(float* __restrict__ out) {
    int i = blockIdx.x * blockDim.x + threadIdx.x;   // BH*NT*D = 81920
    if (i >= BH * NT * Dq) return;
    int d = i & 63;
    int u = (i >> 6) % NT;
    int bh = (i >> 6) / NT;
    float s = 0.f;
    #pragma unroll
    for (int ks = 0; ks < 8; ks++)
        s += g_part[(((size_t)ks * BH + bh) * NT + u) * Dq + d];
    int qi = g_top[bh * NT + u];
    out[((size_t)bh * Lq + qi) * Dq + d] = s;
}

// ---------------- launch ---------------------------------------------------
extern "C" void kernel_launch(void* const* d_in, const int* in_sizes, int n_in,
                              void* d_out, int out_size) {
    const float* Q = (const float*)d_in[0];
    const float* K = (const float*)d_in[1];
    const float* V = (const float*)d_in[2];
    const int* idxs = (const int*)d_in[3];
    float* out = (float*)d_out;

    k_M<<<(BH * Lq) / 8, 256>>>(Q, K, idxs);
    k_topk<<<BH, 256>>>();
    k_vmean<<<BH, 256>>>(V);
    k_fill<<<(BH * Lq * Dq) / 1024, 1024>>>(out);
    k_scores<<<BH * 16, 256>>>(Q, K);
    k_softmax<<<BH * NT, 256>>>();
    k_ctx<<<BH * 8, 256>>>(V);
    k_scatter<<<(BH * NT * Dq + 255) / 256, 256>>>(out);
}

// round 2
// speedup vs baseline: 1.0615x; 1.0615x over previous
#include <cuda_runtime.h>
#include <cuda_bf16.h>
#include <math_constants.h>

// Problem constants (fixed by setup_inputs)
#define Bq 4
#define Hq 8
#define BH 32          // B*H
#define Lq 2048
#define Dq 64
#define SK 40          // sample_k
#define NT 40          // n_top
#define SCALE 0.125f   // 1/sqrt(64)

// ---------------- scratch (device globals; no allocation) ----------------
__device__ float g_M[BH * Lq];                 // 256 KB
__device__ int   g_top[BH * NT];               // 5 KB
__device__ float g_vmean[BH * Dq];             // 8 KB
__device__ float g_scores[(size_t)BH * NT * Lq];   // 10.5 MB
__device__ float g_part[8 * BH * NT * Dq];     // 2.6 MB (k-split partials)

// ---------------- kernel 1: M[bh,l] = max_s q.k - sum_s/L ----------------
// Warp per query. 8 samples batched: 8 independent LDG.64 in flight, then
// 8 parallel butterfly reductions (shuffles pipeline instead of serializing).
__global__ void k_M(const float* __restrict__ Q, const float* __restrict__ K,
                    const int* __restrict__ idxs) {
    int w = blockIdx.x * 8 + (threadIdx.x >> 5);   // query id (bh*2048 + l)
    int lane = threadIdx.x & 31;
    int bh = w >> 11;
    int l  = w & (Lq - 1);
    float2 q = ((const float2*)(Q + (size_t)w * Dq))[lane];
    const float* Kb = K + (size_t)bh * Lq * Dq;
    // coalesced index row load, broadcast later via shfl
    int e0 = idxs[l * SK + lane];                      // s = lane (0..31)
    int e1 = (lane < 8) ? idxs[l * SK + 32 + lane] : 0; // s = 32+lane
    float mx = -CUDART_INF_F;
    float sm = 0.f;
    #pragma unroll
    for (int s0 = 0; s0 < SK; s0 += 8) {
        float p[8];
        #pragma unroll
        for (int j = 0; j < 8; j++) {
            int s = s0 + j;
            int idx = (s < 32) ? __shfl_sync(0xffffffffu, e0, s)
                               : __shfl_sync(0xffffffffu, e1, s - 32);
            float2 k = ((const float2*)(Kb + (size_t)idx * Dq))[lane];
            p[j] = q.x * k.x + q.y * k.y;
        }
        #pragma unroll
        for (int o = 16; o; o >>= 1) {
            #pragma unroll
            for (int j = 0; j < 8; j++)
                p[j] += __shfl_xor_sync(0xffffffffu, p[j], o);
        }
        #pragma unroll
        for (int j = 0; j < 8; j++) { mx = fmaxf(mx, p[j]); sm += p[j]; }
    }
    if (lane == 0) g_M[w] = mx - sm * (1.0f / (float)Lq);
}

// ---------------- kernel 2: top-40 per (b,h) (iterative argmax) ----------
__global__ void k_topk() {
    __shared__ float vals[Lq];
    __shared__ float wv[8];
    __shared__ int   wi[8];
    int bh = blockIdx.x;
    int t = threadIdx.x;
    for (int i = t; i < Lq; i += 256) vals[i] = g_M[bh * Lq + i];
    __syncthreads();
    int lane = t & 31, wid = t >> 5;
    for (int it = 0; it < NT; it++) {
        float bv = -CUDART_INF_F; int bi = Lq;
        for (int i = t; i < Lq; i += 256) {
            float v = vals[i];
            if (v > bv) { bv = v; bi = i; }
        }
        #pragma unroll
        for (int o = 16; o; o >>= 1) {
            float ov = __shfl_xor_sync(0xffffffffu, bv, o);
            int   oi = __shfl_xor_sync(0xffffffffu, bi, o);
            if (ov > bv || (ov == bv && oi < bi)) { bv = ov; bi = oi; }
        }
        if (lane == 0) { wv[wid] = bv; wi[wid] = bi; }
        __syncthreads();
        if (t == 0) {
            for (int wN = 1; wN < 8; wN++)
                if (wv[wN] > bv || (wv[wN] == bv && wi[wN] < bi)) { bv = wv[wN]; bi = wi[wN]; }
            g_top[bh * NT + it] = bi;
            vals[bi] = -CUDART_INF_F;
        }
        __syncthreads();
    }
}

// ---------------- kernel 3: V mean over L per (b,h), float4 --------------
__global__ void k_vmean(const float* __restrict__ V) {
    int bh = blockIdx.x;
    int t = threadIdx.x;               // 256
    int d4 = t & 15, part = t >> 4;    // 16 parts x 128 rows
    const float4* Vb = (const float4*)(V + (size_t)bh * Lq * Dq);
    float4 s = make_float4(0.f, 0.f, 0.f, 0.f);
    int k0 = part * 128;
    for (int k = k0; k < k0 + 128; k++) {
        float4 v = Vb[(size_t)k * 16 + d4];
        s.x += v.x; s.y += v.y; s.z += v.z; s.w += v.w;
    }
    __shared__ float4 ps[256];
    ps[t] = s;
    __syncthreads();
    if (t < 16) {
        float4 a = ps[t];
        #pragma unroll
        for (int pI = 1; pI < 16; pI++) {
            float4 v = ps[pI * 16 + t];
            a.x += v.x; a.y += v.y; a.z += v.z; a.w += v.w;
        }
        const float inv = 1.0f / (float)Lq;
        a.x *= inv; a.y *= inv; a.z *= inv; a.w *= inv;
        ((float4*)g_vmean)[bh * 16 + t] = a;
    }
}

// ---------------- kernel 4: broadcast V_mean to every output row ---------
__global__ void k_fill(float4* __restrict__ out4) {
    int i = blockIdx.x * 256 + threadIdx.x;     // BH*L*16 = 1048576 float4s
    int bh = i >> 15;                            // 2048 rows * 16 f4 per bh
    int d4 = i & 15;
    out4[i] = ((const float4*)g_vmean)[bh * 16 + d4];
}

// ---------------- kernel 5: scores_top = (Q_top @ K^T) * scale -----------
// grid: BH * 16 key-tiles; block 256. tile = 40u x 128k, K-dim = 64 in one slab.
__global__ void k_scores(const float* __restrict__ Q, const float* __restrict__ K) {
    __shared__ float qs[NT * Dq];           // 40x64
    __shared__ float Kt[Dq * 132];          // transposed [d][k], padded row 132
    int bh = blockIdx.x >> 4;
    int kt = blockIdx.x & 15;
    int t = threadIdx.x;
    const float* Qb = Q + (size_t)bh * Lq * Dq;
    const float* Kb = K + (size_t)bh * Lq * Dq;
    for (int j = t; j < NT * Dq; j += 256) {
        int u = j >> 6, d = j & 63;
        int qi = __ldg(&g_top[bh * NT + u]);
        qs[j] = Qb[(size_t)qi * Dq + d];
    }
    for (int j = t; j < 128 * Dq; j += 256) {
        int r = j >> 6, d = j & 63;
        Kt[d * 132 + r] = Kb[(size_t)(kt * 128 + r) * Dq + d];
    }
    __syncthreads();
    int tu = t >> 5;
    int tk = t & 31;
    float acc[5][4] = {};
    #pragma unroll 8
    for (int d = 0; d < Dq; d++) {
        float a[5];
        #pragma unroll
        for (int i = 0; i < 5; i++) a[i] = qs[(tu * 5 + i) * Dq + d];
        float4 b = *(const float4*)&Kt[d * 132 + tk * 4];
        #pragma unroll
        for (int i = 0; i < 5; i++) {
            acc[i][0] = fmaf(a[i], b.x, acc[i][0]);
            acc[i][1] = fmaf(a[i], b.y, acc[i][1]);
            acc[i][2] = fmaf(a[i], b.z, acc[i][2]);
            acc[i][3] = fmaf(a[i], b.w, acc[i][3]);
        }
    }
    #pragma unroll
    for (int i = 0; i < 5; i++) {
        int u = tu * 5 + i;
        float4 r;
        r.x = acc[i][0] * SCALE; r.y = acc[i][1] * SCALE;
        r.z = acc[i][2] * SCALE; r.w = acc[i][3] * SCALE;
        *(float4*)&g_scores[((size_t)(bh * NT + u)) * Lq + kt * 128 + tk * 4] = r;
    }
}

// ---------------- kernel 6: softmax over 2048 keys per top row -----------
__global__ void k_softmax() {
    __shared__ float red[8];
    int row = blockIdx.x;                  // BH*NT = 1280 rows
    float* s = g_scores + (size_t)row * Lq;
    int t = threadIdx.x, lane = t & 31, wid = t >> 5;
    float mx = -CUDART_INF_F;
    for (int i = t; i < Lq; i += 256) mx = fmaxf(mx, s[i]);
    #pragma unroll
    for (int o = 16; o; o >>= 1) mx = fmaxf(mx, __shfl_xor_sync(0xffffffffu, mx, o));
    if (lane == 0) red[wid] = mx;
    __syncthreads();
    mx = red[0];
    #pragma unroll
    for (int i = 1; i < 8; i++) mx = fmaxf(mx, red[i]);
    __syncthreads();
    float sum = 0.f;
    for (int i = t; i < Lq; i += 256) {
        float e = __expf(s[i] - mx);
        s[i] = e;
        sum += e;
    }
    #pragma unroll
    for (int o = 16; o; o >>= 1) sum += __shfl_xor_sync(0xffffffffu, sum, o);
    if (lane == 0) red[wid] = sum;
    __syncthreads();
    sum = 0.f;
    #pragma unroll
    for (int i = 0; i < 8; i++) sum += red[i];
    float inv = 1.0f / sum;
    for (int i = t; i < Lq; i += 256) s[i] *= inv;
}

// ---------------- kernel 7: ctx partial = attn @ V (k-split) -------------
__global__ void k_ctx(const float* __restrict__ V) {
    __shared__ float Vs[128 * Dq];          // 32 KB
    int bh = blockIdx.x >> 3;
    int ks = blockIdx.x & 7;
    int t = threadIdx.x;
    int tu = t >> 5;
    int td = t & 31;
    const float* Vb = V + (size_t)bh * Lq * Dq;
    const float* Sb = g_scores + (size_t)bh * NT * Lq;
    float acc[5][2] = {};
    for (int sub = 0; sub < 2; sub++) {
        int k0 = ks * 256 + sub * 128;
        __syncthreads();
        for (int j = t; j < 128 * Dq; j += 256) Vs[j] = Vb[(size_t)k0 * Dq + j];
        __syncthreads();
        #pragma unroll 4
        for (int kk = 0; kk < 128; kk++) {
            float a[5];
            #pragma unroll
            for (int i = 0; i < 5; i++)
                a[i] = __ldg(&Sb[(size_t)(tu * 5 + i) * Lq + k0 + kk]);
            float2 v = *(const float2*)&Vs[kk * Dq + td * 2];
            #pragma unroll
            for (int i = 0; i < 5; i++) {
                acc[i][0] = fmaf(a[i], v.x, acc[i][0]);
                acc[i][1] = fmaf(a[i], v.y, acc[i][1]);
            }
        }
    }
    #pragma unroll
    for (int i = 0; i < 5; i++) {
        int u = tu * 5 + i;
        float2 r; r.x = acc[i][0]; r.y = acc[i][1];
        *(float2*)&g_part[(((size_t)ks * BH + bh) * NT + u) * Dq + td * 2] = r;
    }
}

// ---------------- kernel 8: sum partials, scatter into output rows -------
__global__ void k_scatter(float* __restrict__ out) {
    int i = blockIdx.x * blockDim.x + threadIdx.x;   // BH*NT*D = 81920
    if (i >= BH * NT * Dq) return;
    int d = i & 63;
    int u = (i >> 6) % NT;
    int bh = (i >> 6) / NT;
    float s = 0.f;
    #pragma unroll
    for (int ks = 0; ks < 8; ks++)
        s += g_part[(((size_t)ks * BH + bh) * NT + u) * Dq + d];
    int qi = g_top[bh * NT + u];
    out[((size_t)bh * Lq + qi) * Dq + d] = s;
}

// ---------------- launch ---------------------------------------------------
extern "C" void kernel_launch(void* const* d_in, const int* in_sizes, int n_in,
                              void* d_out, int out_size) {
    const float* Q = (const float*)d_in[0];
    const float* K = (const float*)d_in[1];
    const float* V = (const float*)d_in[2];
    const int* idxs = (const int*)d_in[3];
    float* out = (float*)d_out;

    k_M<<<(BH * Lq) / 8, 256>>>(Q, K, idxs);
    k_topk<<<BH, 256>>>();
    k_vmean<<<BH, 256>>>(V);
    k_fill<<<(BH * Lq * Dq / 4) / 256, 256>>>((float4*)out);
    k_scores<<<BH * 16, 256>>>(Q, K);
    k_softmax<<<BH * NT, 256>>>();
    k_ctx<<<BH * 8, 256>>>(V);
    k_scatter<<<(BH * NT * Dq + 255) / 256, 256>>>(out);
}